// round 2
// baseline (speedup 1.0000x reference)
#include <cuda_runtime.h>
#include <math.h>

#define B_ 8
#define T_ 1024
#define C_ 32
#define F_ 256
#define D_ 128
#define K_ 512
#define Q_ (B_*T_)      // 8192

// ---------------- scratch (no allocations allowed) ----------------
__device__ float g_G[C_*F_];
__device__ float g_S[F_];
__device__ float g_acc[2];   // [0] = sum E^2, [1] = sum (h-z)^2

#define ABSMASK 0x7fffffff7fffffffULL

__device__ __forceinline__ unsigned long long f32x2_add(unsigned long long a,
                                                        unsigned long long b) {
    unsigned long long r;
    asm("add.rn.f32x2 %0, %1, %2;" : "=l"(r) : "l"(a), "l"(b));
    return r;
}

// ---------------- zero accumulators ----------------
__global__ void zero_kernel() {
    int g = blockIdx.x * 256 + threadIdx.x;
    if (g < C_*F_) g_G[g] = 0.f;
    if (g < F_)    g_S[g] = 0.f;
    if (g < 2)     g_acc[g] = 0.f;
}

// ---------------- fused L1-NN search (all K in-CTA) + quantization loss ----
// 256 CTAs x 256 threads. CTA = 32 queries x all 512 codewords (4 chunks of 128).
// Per-thread tile: 2 queries x 8 codewords, computed with packed f32x2 adds:
//   diff = h2 + (-m2)  [fma pipe], abs = and.b64 [alu pipe], acc += [fma pipe]
// smem: h duplicated (h,h) pairs 32KB + negated m chunk 64KB = 96KB dynamic.
__global__ void nn2_kernel(const float* __restrict__ H, const float* __restrict__ M) {
    extern __shared__ char smem[];
    float2* h2_s = (float2*)smem;                  // [128][32] duplicated
    float*  m_s  = (float*)(smem + 32*1024);       // [128][128] negated chunk

    int tid = threadIdx.x;
    int q0 = blockIdx.x * 32;
    int b  = q0 >> 10;
    int t0 = q0 & (T_ - 1);

    // fill h duplicated: (h, h) so one LDS.128 feeds two f32x2 lanes per query pair
    for (int e = tid; e < D_*32; e += 256) {
        int d = e >> 5, q = e & 31;
        float v = H[b*(D_*T_) + d*T_ + t0 + q];
        h2_s[d*32 + q] = make_float2(v, v);
    }

    int tk = tid & 15, tq = tid >> 4;   // 16 k-groups x 16 q-groups
    int qq = tq * 2, kk = tk * 8;

    float bd0 = 3.4e38f, bd1 = 3.4e38f;
    int   bi0 = 0,       bi1 = 0;

    for (int ch = 0; ch < 4; ch++) {
        __syncthreads();
        // fill negated m chunk: codewords [ch*128, ch*128+128)
        for (int e = tid; e < (D_*128)/4; e += 256) {
            int d = e >> 5, c4 = e & 31;
            float4 mv = *(const float4*)&M[d*K_ + ch*128 + c4*4];
            *(float4*)&m_s[d*128 + c4*4] = make_float4(-mv.x, -mv.y, -mv.z, -mv.w);
        }
        __syncthreads();

        unsigned long long a0=0ULL,a1=0ULL,a2=0ULL,a3=0ULL,a4=0ULL,a5=0ULL,a6=0ULL,a7=0ULL;
        #pragma unroll 4
        for (int d = 0; d < D_; d++) {
            ulonglong2 hh = *(const ulonglong2*)&h2_s[d*32 + qq];       // (h0,h0),(h1,h1)
            ulonglong2 m0 = *(const ulonglong2*)&m_s[d*128 + kk];       // (-k0,-k1),(-k2,-k3)
            ulonglong2 m1 = *(const ulonglong2*)&m_s[d*128 + kk + 4];   // (-k4,-k5),(-k6,-k7)
            unsigned long long t;
            t = f32x2_add(hh.x, m0.x) & ABSMASK; a0 = f32x2_add(a0, t);
            t = f32x2_add(hh.x, m0.y) & ABSMASK; a1 = f32x2_add(a1, t);
            t = f32x2_add(hh.x, m1.x) & ABSMASK; a2 = f32x2_add(a2, t);
            t = f32x2_add(hh.x, m1.y) & ABSMASK; a3 = f32x2_add(a3, t);
            t = f32x2_add(hh.y, m0.x) & ABSMASK; a4 = f32x2_add(a4, t);
            t = f32x2_add(hh.y, m0.y) & ABSMASK; a5 = f32x2_add(a5, t);
            t = f32x2_add(hh.y, m1.x) & ABSMASK; a6 = f32x2_add(a6, t);
            t = f32x2_add(hh.y, m1.y) & ABSMASK; a7 = f32x2_add(a7, t);
        }

        // unpack + thread-local lexmin (k ascending, strict < keeps lowest index)
        int kb = ch*128 + kk;
        unsigned long long aq0[4] = {a0,a1,a2,a3};
        unsigned long long aq1[4] = {a4,a5,a6,a7};
        float cbd0 = 3.4e38f, cbd1 = 3.4e38f;
        int   cbi0 = 0,       cbi1 = 0;
        #pragma unroll
        for (int j = 0; j < 4; j++) {
            float lo = __uint_as_float((unsigned)(aq0[j] & 0xffffffffu));
            float hi = __uint_as_float((unsigned)(aq0[j] >> 32));
            if (lo < cbd0) { cbd0 = lo; cbi0 = kb + 2*j; }
            if (hi < cbd0) { cbd0 = hi; cbi0 = kb + 2*j + 1; }
            lo = __uint_as_float((unsigned)(aq1[j] & 0xffffffffu));
            hi = __uint_as_float((unsigned)(aq1[j] >> 32));
            if (lo < cbd1) { cbd1 = lo; cbi1 = kb + 2*j; }
            if (hi < cbd1) { cbd1 = hi; cbi1 = kb + 2*j + 1; }
        }
        // lexicographic min across the 16 tk lanes (first-argmin semantics)
        #pragma unroll
        for (int off = 1; off < 16; off <<= 1) {
            float od = __shfl_xor_sync(0xffffffffu, cbd0, off);
            int   oi = __shfl_xor_sync(0xffffffffu, cbi0, off);
            if (od < cbd0 || (od == cbd0 && oi < cbi0)) { cbd0 = od; cbi0 = oi; }
            od = __shfl_xor_sync(0xffffffffu, cbd1, off);
            oi = __shfl_xor_sync(0xffffffffu, cbi1, off);
            if (od < cbd1 || (od == cbd1 && oi < cbi1)) { cbd1 = od; cbi1 = oi; }
        }
        // chunks ascend in k: strict < keeps the earlier (lower-index) chunk on ties
        if (cbd0 < bd0) { bd0 = cbd0; bi0 = cbi0; }
        if (cbd1 < bd1) { bd1 = cbd1; bi1 = cbi1; }
    }

    // quantization loss: sum_d (h - M[d, bi])^2, tk lanes parallelize over d
    float s0 = 0.f, s1 = 0.f;
    #pragma unroll
    for (int i = 0; i < 8; i++) {
        int d = tk + i*16;
        float h0 = h2_s[d*32 + qq].x;
        float h1 = h2_s[d*32 + qq + 1].x;
        float z0 = M[d*K_ + bi0];
        float z1 = M[d*K_ + bi1];
        float e0 = h0 - z0, e1 = h1 - z1;
        s0 += e0*e0; s1 += e1*e1;
    }
    #pragma unroll
    for (int off = 1; off < 16; off <<= 1) {
        s0 += __shfl_xor_sync(0xffffffffu, s0, off);
        s1 += __shfl_xor_sync(0xffffffffu, s1, off);
    }
    if (tk == 0) atomicAdd(&g_acc[1], s0 + s1);
}

// ---------------- fused decoder: E = Hdec W^T - X, sumE^2, S, G partials ----
// 128 CTAs x 256 threads, 64 rows each. Hdec tile staged in smem ONCE.
__global__ void dec_kernel(const float* __restrict__ Hdec, const float* __restrict__ W,
                           const float* __restrict__ X) {
    extern __shared__ char smem[];
    float* hd_s = (float*)smem;                    // [64][256]  64KB
    float* e_s  = (float*)(smem + 65536);          // [64][32]    8KB
    float* w_s  = (float*)(smem + 65536 + 8192);   // [256][33]  33KB (padded)
    __shared__ float red[8];

    int tid = threadIdx.x;
    int r0 = blockIdx.x * 64;

    for (int e = tid; e < C_*F_; e += 256) {
        int c = e >> 8, f = e & 255;
        w_s[f*33 + c] = W[e];
    }
    {
        const float4* src = (const float4*)(Hdec + (size_t)r0 * F_);
        float4* dst = (float4*)hd_s;
        #pragma unroll
        for (int i = 0; i < 16; i++) dst[tid + i*256] = src[tid + i*256];
    }
    __syncthreads();

    // phase 2: E tile + sumE^2. warp = 8-row group, lane = channel c
    int warp = tid >> 5, lane = tid & 31;
    float acc[8] = {0,0,0,0,0,0,0,0};
    for (int f = 0; f < F_; f += 4) {
        float w0 = w_s[(f+0)*33 + lane];
        float w1 = w_s[(f+1)*33 + lane];
        float w2 = w_s[(f+2)*33 + lane];
        float w3 = w_s[(f+3)*33 + lane];
        #pragma unroll
        for (int i = 0; i < 8; i++) {
            float4 h4 = *(const float4*)&hd_s[(warp*8 + i)*F_ + f];
            acc[i] = fmaf(h4.x, w0, fmaf(h4.y, w1, fmaf(h4.z, w2, fmaf(h4.w, w3, acc[i]))));
        }
    }
    float s2 = 0.f;
    #pragma unroll
    for (int i = 0; i < 8; i++) {
        int lr = warp*8 + i;
        float ev = acc[i] - X[(size_t)(r0 + lr)*C_ + lane];
        e_s[lr*C_ + lane] = ev;
        s2 += ev * ev;
    }
    #pragma unroll
    for (int off = 16; off > 0; off >>= 1) s2 += __shfl_down_sync(0xffffffffu, s2, off);
    if (lane == 0) red[warp] = s2;
    __syncthreads();   // also guards e_s for phase 4
    if (tid == 0) {
        float tot = 0.f;
        #pragma unroll
        for (int i = 0; i < 8; i++) tot += red[i];
        atomicAdd(&g_acc[0], tot);
    }

    // phase 3: S[f] partial (tid == f)
    {
        float ssum = 0.f;
        #pragma unroll 8
        for (int r = 0; r < 64; r++) ssum += hd_s[r*F_ + tid];
        atomicAdd(&g_S[tid], ssum);
    }

    // phase 4: G[c,f] partial = sum_r e_s[r][c] * hd_s[r][f]
    {
        int c = tid >> 3, fq = tid & 7, f0 = fq * 32;
        float ga[32];
        #pragma unroll
        for (int j = 0; j < 32; j++) ga[j] = 0.f;
        for (int r = 0; r < 64; r++) {
            float ev = e_s[r*C_ + c];
            #pragma unroll
            for (int j = 0; j < 8; j++) {
                float4 h4 = *(const float4*)&hd_s[r*F_ + f0 + j*4];
                ga[j*4+0] += ev * h4.x;
                ga[j*4+1] += ev * h4.y;
                ga[j*4+2] += ev * h4.z;
                ga[j*4+3] += ev * h4.w;
            }
        }
        #pragma unroll
        for (int j = 0; j < 32; j++) atomicAdd(&g_G[c*F_ + f0 + j], ga[j]);
    }
}

// ---------------- final scalar assembly ----------------
__global__ void final_kernel(const float* __restrict__ W, const float* __restrict__ w_d,
                             float* __restrict__ out) {
    __shared__ float red[256];
    int tid = threadIdx.x;

    float s = 0.f;
    for (int i = tid; i < C_*F_; i += 256) { float v = g_G[i]; s += v*v; }
    red[tid] = s; __syncthreads();
    for (int o = 128; o > 0; o >>= 1) { if (tid < o) red[tid] += red[tid+o]; __syncthreads(); }
    float sumG2 = red[0]; __syncthreads();

    float sv = g_S[tid];
    red[tid] = sv * sv; __syncthreads();
    for (int o = 128; o > 0; o >>= 1) { if (tid < o) red[tid] += red[tid+o]; __syncthreads(); }
    float sumS2 = red[0]; __syncthreads();

    red[tid] = (tid < C_) ? w_d[tid]*w_d[tid] : 0.f; __syncthreads();
    for (int o = 128; o > 0; o >>= 1) { if (tid < o) red[tid] += red[tid+o]; __syncthreads(); }
    float sumwd2 = red[0]; __syncthreads();

    s = 0.f;
    for (int i = tid; i < C_*F_; i += 256) s += W[i] * g_S[i & 255] * w_d[i >> 8];
    red[tid] = s; __syncthreads();
    for (int o = 128; o > 0; o >>= 1) { if (tid < o) red[tid] += red[tid+o]; __syncthreads(); }
    float dotWS = red[0];

    if (tid == 0) {
        float loss_rec = g_acc[0] / 262144.f;                   // mean over B*T*C
        float loss_m   = 2.f * g_acc[1] / 1048576.f;            // 2*sum/(B*D*T)
        float normGrec = (2.f / 262144.f) * sqrtf(sumG2);       // ||g_rec||_F
        float normGd   = sqrtf(sumwd2) * sqrtf(sumS2) / 8192.f; // ||g_d||_F (rank-1)
        float lmbda    = normGrec / (normGd + 1e-6f);
        float loss_d   = -dotWS / 8192.f;
        out[0] = loss_rec + loss_m + lmbda * loss_d;
    }
}

extern "C" void kernel_launch(void* const* d_in, const int* in_sizes, int n_in,
                              void* d_out, int out_size) {
    const float* X    = (const float*)d_in[0];
    const float* H    = (const float*)d_in[1];
    const float* M    = (const float*)d_in[2];
    const float* Hdec = (const float*)d_in[3];
    const float* W    = (const float*)d_in[4];
    const float* w_d  = (const float*)d_in[5];
    float* out = (float*)d_out;
    (void)in_sizes; (void)n_in; (void)out_size;

    static int attr_done = 0;
    if (!attr_done) {
        cudaFuncSetAttribute(nn2_kernel, cudaFuncAttributeMaxDynamicSharedMemorySize, 98304);
        cudaFuncSetAttribute(dec_kernel, cudaFuncAttributeMaxDynamicSharedMemorySize, 110592);
        attr_done = 1;
    }

    zero_kernel <<<32, 256>>>();
    nn2_kernel  <<<Q_/32, 256, 98304>>>(H, M);        // 256 CTAs: the hot kernel
    dec_kernel  <<<Q_/64, 256, 110592>>>(Hdec, W, X); // 128 CTAs
    final_kernel<<<1, 256>>>(W, w_d, out);
}

// round 3
// speedup vs baseline: 1.3442x; 1.3442x over previous
#include <cuda_runtime.h>
#include <math.h>

#define B_ 8
#define T_ 1024
#define C_ 32
#define F_ 256
#define D_ 128
#define K_ 512
#define Q_ (B_*T_)      // 8192
#define KC 64
#define NKC (K_/KC)     // 8
#define QT 32
#define NQT (Q_/QT)     // 256

// ---------------- scratch (no allocations allowed) ----------------
__device__ float g_bd[NKC*Q_];
__device__ int   g_bi[NKC*Q_];
__device__ float g_G[C_*F_];
__device__ float g_S[F_];
__device__ float g_acc[2];   // [0] = sum E^2, [1] = sum (h-z)^2

__device__ __forceinline__ float2 fadd2(float2 a, float2 b) {
    float2 r;
    asm("add.rn.f32x2 %0, %1, %2;"
        : "=l"(reinterpret_cast<unsigned long long&>(r))
        : "l"(reinterpret_cast<unsigned long long&>(a)),
          "l"(reinterpret_cast<unsigned long long&>(b)));
    return r;
}

// ---------------- zero accumulators ----------------
__global__ void zero_kernel() {
    int g = blockIdx.x * 256 + threadIdx.x;
    if (g < C_*F_) g_G[g] = 0.f;
    if (g < F_)    g_S[g] = 0.f;
    if (g < 2)     g_acc[g] = 0.f;
}

// ---------------- L1 NN search: packed-diff + abs-accumulate ----------------
// 2048 CTAs (256 q-tiles x 8 k-chunks), 256 threads. CTA = 32 queries x 64 codewords.
// smem: h duplicated as (h,h) float2 pairs [128][32] = 32KB, negated m [128][64] = 32KB.
// Inner: diff = add.rn.f32x2(hh, -mm) [1 fma instr / 2 elems], acc += |t| [FADD w/ free abs].
__global__ void nn3_kernel(const float* __restrict__ H, const float* __restrict__ M) {
    extern __shared__ char smem[];
    float2* h2_s = (float2*)smem;              // [128][32] (h,h)
    float*  m_s  = (float*)(smem + 32*1024);   // [128][64] negated

    int tid = threadIdx.x;
    int qt = blockIdx.x & (NQT - 1);
    int kc = blockIdx.x >> 8;
    int q0 = qt * QT;
    int b  = q0 >> 10;
    int t0 = q0 & (T_ - 1);
    int k0 = kc * KC;

    for (int e = tid; e < D_*QT; e += 256) {
        int d = e >> 5, q = e & 31;
        float v = H[b*(D_*T_) + d*T_ + t0 + q];
        h2_s[e] = make_float2(v, v);
    }
    for (int e = tid; e < (D_*KC)/4; e += 256) {
        int d = e >> 4, c4 = e & 15;
        float4 mv = *(const float4*)&M[d*K_ + k0 + c4*4];
        *(float4*)&m_s[d*KC + c4*4] = make_float4(-mv.x, -mv.y, -mv.z, -mv.w);
    }
    __syncthreads();

    int tk = tid & 15, tq = tid >> 4;   // 16 k-groups x 16 q-groups
    int qq = tq * 2, kk = tk * 4;       // 16B-consecutive m loads: conflict-free

    float d00=0.f,d01=0.f,d02=0.f,d03=0.f,d10=0.f,d11=0.f,d12=0.f,d13=0.f;
    #pragma unroll 4
    for (int d = 0; d < D_; d++) {
        float4 hh = *(const float4*)&h2_s[d*QT + qq];   // (h0,h0,h1,h1)
        float4 mm = *(const float4*)&m_s[d*KC + kk];    // (-k0,-k1,-k2,-k3)
        float2 t;
        t = fadd2(make_float2(hh.x, hh.y), make_float2(mm.x, mm.y));
        d00 += fabsf(t.x); d01 += fabsf(t.y);
        t = fadd2(make_float2(hh.x, hh.y), make_float2(mm.z, mm.w));
        d02 += fabsf(t.x); d03 += fabsf(t.y);
        t = fadd2(make_float2(hh.z, hh.w), make_float2(mm.x, mm.y));
        d10 += fabsf(t.x); d11 += fabsf(t.y);
        t = fadd2(make_float2(hh.z, hh.w), make_float2(mm.z, mm.w));
        d12 += fabsf(t.x); d13 += fabsf(t.y);
    }
    // thread-local lexmin (k ascending, strict < keeps lowest index)
    float bd0 = d00; int bi0 = k0 + kk;
    if (d01 < bd0) { bd0 = d01; bi0 = k0 + kk + 1; }
    if (d02 < bd0) { bd0 = d02; bi0 = k0 + kk + 2; }
    if (d03 < bd0) { bd0 = d03; bi0 = k0 + kk + 3; }
    float bd1 = d10; int bi1 = k0 + kk;
    if (d11 < bd1) { bd1 = d11; bi1 = k0 + kk + 1; }
    if (d12 < bd1) { bd1 = d12; bi1 = k0 + kk + 2; }
    if (d13 < bd1) { bd1 = d13; bi1 = k0 + kk + 3; }
    // lexicographic min across the 16 tk lanes
    #pragma unroll
    for (int off = 1; off < 16; off <<= 1) {
        float od = __shfl_xor_sync(0xffffffffu, bd0, off);
        int   oi = __shfl_xor_sync(0xffffffffu, bi0, off);
        if (od < bd0 || (od == bd0 && oi < bi0)) { bd0 = od; bi0 = oi; }
        od = __shfl_xor_sync(0xffffffffu, bd1, off);
        oi = __shfl_xor_sync(0xffffffffu, bi1, off);
        if (od < bd1 || (od == bd1 && oi < bi1)) { bd1 = od; bi1 = oi; }
    }
    if (tk == 0) {
        g_bd[kc*Q_ + q0 + qq    ] = bd0;  g_bi[kc*Q_ + q0 + qq    ] = bi0;
        g_bd[kc*Q_ + q0 + qq + 1] = bd1;  g_bi[kc*Q_ + q0 + qq + 1] = bi1;
    }
}

// ---------------- combine K-chunks, compute sum (h - z)^2 ----------------
__global__ void nnred_kernel(const float* __restrict__ H, const float* __restrict__ M) {
    int tid = threadIdx.x;
    int q = blockIdx.x * 256 + tid;
    float bd = g_bd[q]; int bi = g_bi[q];
    #pragma unroll
    for (int c = 1; c < NKC; c++) {
        float dd = g_bd[c*Q_ + q]; int ii = g_bi[c*Q_ + q];
        if (dd < bd) { bd = dd; bi = ii; }   // chunks ascend in k
    }
    int b = q >> 10, t = q & (T_ - 1);
    const float* h = H + b*(D_*T_) + t;
    float s = 0.f;
    #pragma unroll 8
    for (int d = 0; d < D_; d++) {
        float diff = h[d*T_] - M[d*K_ + bi];
        s += diff * diff;
    }
    #pragma unroll
    for (int off = 16; off > 0; off >>= 1) s += __shfl_down_sync(0xffffffffu, s, off);
    __shared__ float red[8];
    int warp = tid >> 5, lane = tid & 31;
    if (lane == 0) red[warp] = s;
    __syncthreads();
    if (tid == 0) {
        float tot = 0.f;
        #pragma unroll
        for (int i = 0; i < 8; i++) tot += red[i];
        atomicAdd(&g_acc[1], tot);
    }
}

// ---------------- fused decoder: E tile, sumE^2, S partial, G partial ----
// 256 CTAs x 256 threads, 32 rows each. Hdec tile staged in smem once.
__global__ void dec_kernel(const float* __restrict__ Hdec, const float* __restrict__ W,
                           const float* __restrict__ X) {
    extern __shared__ char smem[];
    float* hd_s = (float*)smem;                    // [32][256]  32KB
    float* e_s  = (float*)(smem + 32768);          // [32][32]    4KB
    float* w_s  = (float*)(smem + 32768 + 4096);   // [256][33]  33KB padded
    __shared__ float red[8];

    int tid = threadIdx.x;
    int r0 = blockIdx.x * 32;
    int warp = tid >> 5, lane = tid & 31;

    for (int e = tid; e < C_*F_; e += 256) {
        int c = e >> 8, f = e & 255;
        w_s[f*33 + c] = W[e];
    }
    {
        const float4* src = (const float4*)(Hdec + (size_t)r0 * F_);
        float4* dst = (float4*)hd_s;
        #pragma unroll
        for (int i = 0; i < 8; i++) dst[tid + i*256] = src[tid + i*256];
    }
    __syncthreads();

    // phase 2: E = Hdec W^T - X, sumE^2. warp = 4-row group, lane = channel c
    float acc[4] = {0,0,0,0};
    for (int f = 0; f < F_; f += 4) {
        float w0 = w_s[(f+0)*33 + lane];
        float w1 = w_s[(f+1)*33 + lane];
        float w2 = w_s[(f+2)*33 + lane];
        float w3 = w_s[(f+3)*33 + lane];
        #pragma unroll
        for (int i = 0; i < 4; i++) {
            float4 h4 = *(const float4*)&hd_s[(warp*4 + i)*F_ + f];   // warp-broadcast
            acc[i] = fmaf(h4.x, w0, fmaf(h4.y, w1, fmaf(h4.z, w2, fmaf(h4.w, w3, acc[i]))));
        }
    }
    float s2 = 0.f;
    #pragma unroll
    for (int i = 0; i < 4; i++) {
        int lr = warp*4 + i;
        float ev = acc[i] - X[(size_t)(r0 + lr)*C_ + lane];
        e_s[lr*C_ + lane] = ev;
        s2 += ev * ev;
    }
    #pragma unroll
    for (int off = 16; off > 0; off >>= 1) s2 += __shfl_down_sync(0xffffffffu, s2, off);
    if (lane == 0) red[warp] = s2;
    __syncthreads();   // also publishes e_s for phase 4
    if (tid == 0) {
        float tot = 0.f;
        #pragma unroll
        for (int i = 0; i < 8; i++) tot += red[i];
        atomicAdd(&g_acc[0], tot);
    }

    // phase 3: S[f] partial (tid == f, consecutive lanes -> conflict-free)
    {
        float ssum = 0.f;
        #pragma unroll 8
        for (int r = 0; r < 32; r++) ssum += hd_s[r*F_ + tid];
        atomicAdd(&g_S[tid], ssum);
    }

    // phase 4: G[c,f] partial. warp owns f-block [warp*32, warp*32+32), lane = c.
    // hd reads warp-broadcast, e reads consecutive: conflict-free.
    {
        int f0 = warp * 32;
        float ga[32];
        #pragma unroll
        for (int j = 0; j < 32; j++) ga[j] = 0.f;
        for (int r = 0; r < 32; r++) {
            float ev = e_s[r*C_ + lane];
            #pragma unroll
            for (int j = 0; j < 8; j++) {
                float4 h4 = *(const float4*)&hd_s[r*F_ + f0 + j*4];
                ga[j*4+0] += ev * h4.x;
                ga[j*4+1] += ev * h4.y;
                ga[j*4+2] += ev * h4.z;
                ga[j*4+3] += ev * h4.w;
            }
        }
        #pragma unroll
        for (int j = 0; j < 32; j++) atomicAdd(&g_G[lane*F_ + f0 + j], ga[j]);
    }
}

// ---------------- final scalar assembly (single fused reduction pass) -------
__global__ void final_kernel(const float* __restrict__ W, const float* __restrict__ w_d,
                             float* __restrict__ out) {
    __shared__ float4 red4[256];
    int tid = threadIdx.x;

    float sG = 0.f, sWS = 0.f;
    #pragma unroll 4
    for (int i = tid; i < C_*F_; i += 256) {
        float g = g_G[i];
        sG  += g * g;
        sWS += W[i] * g_S[i & 255] * w_d[i >> 8];
    }
    float sv  = g_S[tid];
    float sS  = sv * sv;
    float wd2 = (tid < C_) ? w_d[tid]*w_d[tid] : 0.f;

    red4[tid] = make_float4(sG, sWS, sS, wd2);
    __syncthreads();
    for (int o = 128; o > 0; o >>= 1) {
        if (tid < o) {
            float4 a = red4[tid], b = red4[tid + o];
            red4[tid] = make_float4(a.x + b.x, a.y + b.y, a.z + b.z, a.w + b.w);
        }
        __syncthreads();
    }

    if (tid == 0) {
        float4 r = red4[0];
        float loss_rec = g_acc[0] / 262144.f;                 // mean over B*T*C
        float loss_m   = 2.f * g_acc[1] / 1048576.f;          // 2*sum/(B*D*T)
        float normGrec = (2.f / 262144.f) * sqrtf(r.x);       // ||g_rec||_F
        float normGd   = sqrtf(r.w) * sqrtf(r.z) / 8192.f;    // ||g_d||_F (rank-1)
        float lmbda    = normGrec / (normGd + 1e-6f);
        float loss_d   = -r.y / 8192.f;
        out[0] = loss_rec + loss_m + lmbda * loss_d;
    }
}

extern "C" void kernel_launch(void* const* d_in, const int* in_sizes, int n_in,
                              void* d_out, int out_size) {
    const float* X    = (const float*)d_in[0];
    const float* H    = (const float*)d_in[1];
    const float* M    = (const float*)d_in[2];
    const float* Hdec = (const float*)d_in[3];
    const float* W    = (const float*)d_in[4];
    const float* w_d  = (const float*)d_in[5];
    float* out = (float*)d_out;
    (void)in_sizes; (void)n_in; (void)out_size;

    static int attr_done = 0;
    if (!attr_done) {
        cudaFuncSetAttribute(nn3_kernel, cudaFuncAttributeMaxDynamicSharedMemorySize, 65536);
        cudaFuncSetAttribute(dec_kernel, cudaFuncAttributeMaxDynamicSharedMemorySize, 70656);
        attr_done = 1;
    }

    zero_kernel <<<32, 256>>>();
    nn3_kernel  <<<NQT*NKC, 256, 65536>>>(H, M);     // 2048 CTAs: the hot kernel
    nnred_kernel<<<Q_/256, 256>>>(H, M);
    dec_kernel  <<<Q_/32, 256, 70656>>>(Hdec, W, X); // 256 CTAs
    final_kernel<<<1, 256>>>(W, w_d, out);
}